// round 9
// baseline (speedup 1.0000x reference)
#include <cuda_runtime.h>
#include <cuda_fp16.h>

// Problem constants
#define B  2
#define C  256
#define H  200
#define W  336
#define R  1000
#define OH 14
#define OW 14
#define HW (H * W)           // 67200
#define SCALE 0.25f

// NHWC features in fp16: 2*67200*256*2B = 68.8 MB
__device__ static __half g_feat[(size_t)B * HW * C];

// ---------------------------------------------------------------------------
// Kernel 1: NCHW fp32 -> NHWC fp16 transpose (4x4 register micro-transpose,
// XOR-swizzled smem). Source reads streamed (__ldcs): single use.
// ---------------------------------------------------------------------------
#define TSTRIDE 68
__global__ __launch_bounds__(256) void transpose_kernel(const float* __restrict__ src) {
    __shared__ float tileT[64 * TSTRIDE];

    const int batch = blockIdx.z;
    const int p0 = blockIdx.x * 64;
    const int c0 = blockIdx.y * 64;
    const float* s = src + (size_t)batch * C * HW;
    __half*      d = g_feat + (size_t)batch * HW * C;

    {
        const int tx = threadIdx.x & 15;
        const int ty = threadIdx.x >> 4;
        const float* rb = s + (size_t)(c0 + ty * 4) * HW + p0 + tx * 4;
        const float4 v0 = __ldcs((const float4*)(rb));
        const float4 v1 = __ldcs((const float4*)(rb + HW));
        const float4 v2 = __ldcs((const float4*)(rb + 2 * (size_t)HW));
        const float4 v3 = __ldcs((const float4*)(rb + 3 * (size_t)HW));

        float* wb = &tileT[(4 * tx) * TSTRIDE + 4 * ((ty ^ tx) & 15)];
        *(float4*)(wb + 0 * TSTRIDE) = make_float4(v0.x, v1.x, v2.x, v3.x);
        *(float4*)(wb + 1 * TSTRIDE) = make_float4(v0.y, v1.y, v2.y, v3.y);
        *(float4*)(wb + 2 * TSTRIDE) = make_float4(v0.z, v1.z, v2.z, v3.z);
        *(float4*)(wb + 3 * TSTRIDE) = make_float4(v0.w, v1.w, v2.w, v3.w);
    }
    __syncthreads();

    {
        const int c4 = threadIdx.x & 15;
        const int pr = threadIdx.x >> 4;
        #pragma unroll
        for (int k = 0; k < 4; k++) {
            const int p = pr + k * 16;
            const float4 w = *(const float4*)&tileT[p * TSTRIDE + 4 * ((c4 ^ (p >> 2)) & 15)];
            const __half2 h0 = __floats2half2_rn(w.x, w.y);
            const __half2 h1 = __floats2half2_rn(w.z, w.w);
            uint2 u;
            u.x = *reinterpret_cast<const unsigned int*>(&h0);
            u.y = *reinterpret_cast<const unsigned int*>(&h1);
            *reinterpret_cast<uint2*>(d + (size_t)(p0 + p) * C + c0 + c4 * 4) = u;
        }
    }
}

// ---------------------------------------------------------------------------
// Kernel 2: ROI-align gather, one block per ROI. 1024 threads = 32 channel-
// groups (8ch, uint4) x 32 sample-lanes over 196 samples. Sample pairs
// (s, s+98) batched -> 8 LDG.128 in flight. Whole 256x196 tile staged in
// 199 KB dynamic smem with XOR swizzle:
//   quad q at sample s lives at word 128*(q&1) + 4*((q>>1) ^ ((s>>2)&7))
//   - STS.128 (warp = fixed s, cg 0..31): (cg^E) permutation -> conflict-free
//   - writeback LDS.128 (warp = fixed q, jq consecutive): bank group
//     (4jq + (q>>1)^(jq&7) + m) mod 8 bijective in jq -> conflict-free
// Output written fully dense: 4 STG.128 per unit, 784B/channel contiguous.
// ---------------------------------------------------------------------------
#define CPAD 260
#define GATHER_SMEM (196 * CPAD * 4)   // 203840 B

__global__ __launch_bounds__(1024, 1) void roi_gather_kernel(
    const float* __restrict__ rois, float* __restrict__ out)
{
    extern __shared__ float sout[];   // [196][CPAD]

    const int r    = blockIdx.x;
    const int t    = threadIdx.x;
    const int cg   = t & 31;    // channel group: channels 8cg..8cg+7
    const int lane = t >> 5;    // 0..31

    const float bf = __ldg(&rois[r * 5 + 0]);
    const float x1 = __ldg(&rois[r * 5 + 1]);
    const float y1 = __ldg(&rois[r * 5 + 2]);
    const float x2 = __ldg(&rois[r * 5 + 3]);
    const float y2 = __ldg(&rois[r * 5 + 4]);
    const int  b   = (int)bf;

    const uint4* f4 = reinterpret_cast<const uint4*>(g_feat) + (size_t)b * HW * 32;

    // ---- compute phase: sample pairs (si, si+98), MLP=8 ----
    for (int si = lane; si < 98; si += 32) {
        float w00[2], w01[2], w10[2], w11[2];
        int   idx00[2], idx01[2], idx10[2], idx11[2];
        int   srow[2];

        #pragma unroll
        for (int hv = 0; hv < 2; hv++) {
            const int s  = si + hv * 98;
            srow[hv] = s;
            const int oh = s / 14;
            const int ow = s - oh * 14;

            const float gy  = ((float)oh + 0.5f) * (1.0f / OH);
            const float fy  = (y1 + gy * (y2 - y1)) * SCALE - 0.5f;
            const float y0f = floorf(fy);
            const float ly  = fy - y0f;
            const int   yi0 = (int)y0f;
            const int   yi1 = yi0 + 1;
            const float wy0 = (1.0f - ly) * ((yi0 >= 0 && yi0 < H) ? 1.0f : 0.0f);
            const float wy1 = ly * ((yi1 >= 0 && yi1 < H) ? 1.0f : 0.0f);
            const int   y0c = min(max(yi0, 0), H - 1);
            const int   y1c = min(max(yi1, 0), H - 1);

            const float gx  = ((float)ow + 0.5f) * (1.0f / OW);
            const float fx  = (x1 + gx * (x2 - x1)) * SCALE - 0.5f;
            const float x0f = floorf(fx);
            const float lx  = fx - x0f;
            const int   xi0 = (int)x0f;
            const int   xi1 = xi0 + 1;
            const float wx0 = (1.0f - lx) * ((xi0 >= 0 && xi0 < W) ? 1.0f : 0.0f);
            const float wx1 = lx * ((xi1 >= 0 && xi1 < W) ? 1.0f : 0.0f);
            const int   x0c = min(max(xi0, 0), W - 1);
            const int   x1c = min(max(xi1, 0), W - 1);

            w00[hv] = wy0 * wx0; w01[hv] = wy0 * wx1;
            w10[hv] = wy1 * wx0; w11[hv] = wy1 * wx1;
            idx00[hv] = y0c * W + x0c; idx01[hv] = y0c * W + x1c;
            idx10[hv] = y1c * W + x0c; idx11[hv] = y1c * W + x1c;
        }

        // 8 loads in flight
        const uint4 a00 = __ldg(&f4[(size_t)idx00[0] * 32 + cg]);
        const uint4 a01 = __ldg(&f4[(size_t)idx01[0] * 32 + cg]);
        const uint4 a10 = __ldg(&f4[(size_t)idx10[0] * 32 + cg]);
        const uint4 a11 = __ldg(&f4[(size_t)idx11[0] * 32 + cg]);
        const uint4 c00 = __ldg(&f4[(size_t)idx00[1] * 32 + cg]);
        const uint4 c01 = __ldg(&f4[(size_t)idx01[1] * 32 + cg]);
        const uint4 c10 = __ldg(&f4[(size_t)idx10[1] * 32 + cg]);
        const uint4 c11 = __ldg(&f4[(size_t)idx11[1] * 32 + cg]);

        #define BLEND(U00, U01, U10, U11, K, CMP, OA, OB)                                   \
            {                                                                               \
                const float2 ca = __half22float2(*reinterpret_cast<const __half2*>(&U00.CMP)); \
                const float2 cb = __half22float2(*reinterpret_cast<const __half2*>(&U01.CMP)); \
                const float2 cc = __half22float2(*reinterpret_cast<const __half2*>(&U10.CMP)); \
                const float2 cd = __half22float2(*reinterpret_cast<const __half2*>(&U11.CMP)); \
                OA = fmaf(w00[K], ca.x, fmaf(w01[K], cb.x, fmaf(w10[K], cc.x, w11[K] * cd.x))); \
                OB = fmaf(w00[K], ca.y, fmaf(w01[K], cb.y, fmaf(w10[K], cc.y, w11[K] * cd.y))); \
            }

        {
            float o0, o1, o2, o3, o4, o5, o6, o7;
            BLEND(a00, a01, a10, a11, 0, x, o0, o1)
            BLEND(a00, a01, a10, a11, 0, y, o2, o3)
            BLEND(a00, a01, a10, a11, 0, z, o4, o5)
            BLEND(a00, a01, a10, a11, 0, w, o6, o7)
            const int s = srow[0];
            const int E = (s >> 2) & 7;
            float* sb = &sout[s * CPAD];
            *(float4*)(sb + 4 * (cg ^ E))       = make_float4(o0, o1, o2, o3);
            *(float4*)(sb + 128 + 4 * (cg ^ E)) = make_float4(o4, o5, o6, o7);
        }
        {
            float o0, o1, o2, o3, o4, o5, o6, o7;
            BLEND(c00, c01, c10, c11, 1, x, o0, o1)
            BLEND(c00, c01, c10, c11, 1, y, o2, o3)
            BLEND(c00, c01, c10, c11, 1, z, o4, o5)
            BLEND(c00, c01, c10, c11, 1, w, o6, o7)
            const int s = srow[1];
            const int E = (s >> 2) & 7;
            float* sb = &sout[s * CPAD];
            *(float4*)(sb + 4 * (cg ^ E))       = make_float4(o0, o1, o2, o3);
            *(float4*)(sb + 128 + 4 * (cg ^ E)) = make_float4(o4, o5, o6, o7);
        }
        #undef BLEND
    }
    __syncthreads();

    // ---- writeback: 3136 units = 64 quads x 49 sample-quads ----
    // unit u: q = u/49 (channels 4q..4q+3), jq = u%49 (samples 4jq..4jq+3)
    // 4x LDS.128 -> 4x4 register transpose -> 4x STG.128 (dense, streamed)
    float* obase = out + (size_t)r * C * (OH * OW);
    #pragma unroll
    for (int k = 0; k < 4; k++) {
        const int u = t + k * 1024;
        if (u < 3136) {
            const int q  = u / 49;
            const int jq = u - q * 49;
            const int jj0 = jq * 4;
            const int woff = ((q & 1) << 7) + 4 * ((q >> 1) ^ (jq & 7));

            const float4 v0 = *(const float4*)&sout[(jj0 + 0) * CPAD + woff];
            const float4 v1 = *(const float4*)&sout[(jj0 + 1) * CPAD + woff];
            const float4 v2 = *(const float4*)&sout[(jj0 + 2) * CPAD + woff];
            const float4 v3 = *(const float4*)&sout[(jj0 + 3) * CPAD + woff];

            float* ob = obase + (size_t)(q * 4) * (OH * OW) + jj0;
            __stcs((float4*)(ob),                  make_float4(v0.x, v1.x, v2.x, v3.x));
            __stcs((float4*)(ob +     (OH * OW)),  make_float4(v0.y, v1.y, v2.y, v3.y));
            __stcs((float4*)(ob + 2 * (OH * OW)),  make_float4(v0.z, v1.z, v2.z, v3.z));
            __stcs((float4*)(ob + 3 * (OH * OW)),  make_float4(v0.w, v1.w, v2.w, v3.w));
        }
    }
}

// ---------------------------------------------------------------------------
extern "C" void kernel_launch(void* const* d_in, const int* in_sizes, int n_in,
                              void* d_out, int out_size) {
    const float* features = (const float*)d_in[0];
    const float* rois     = (const float*)d_in[1];
    if (n_in >= 2 && in_sizes[0] == R * 5) {
        features = (const float*)d_in[1];
        rois     = (const float*)d_in[0];
    }
    float* out = (float*)d_out;

    cudaFuncSetAttribute(roi_gather_kernel,
                         cudaFuncAttributeMaxDynamicSharedMemorySize, GATHER_SMEM);

    dim3 tgrid(HW / 64, C / 64, B);   // (1050, 4, 2)
    transpose_kernel<<<tgrid, 256>>>(features);

    roi_gather_kernel<<<R, 1024, GATHER_SMEM>>>(rois, out);
}

// round 10
// speedup vs baseline: 1.1533x; 1.1533x over previous
#include <cuda_runtime.h>
#include <cuda_fp16.h>

// Problem constants
#define B  2
#define C  256
#define H  200
#define W  336
#define R  1000
#define OH 14
#define OW 14
#define HW (H * W)           // 67200
#define SCALE 0.25f

// NHWC features in fp16: 2*67200*256*2B = 68.8 MB
__device__ static __half g_feat[(size_t)B * HW * C];

// ---------------------------------------------------------------------------
// Kernel 1: NCHW fp32 -> NHWC fp16 transpose (4x4 register micro-transpose,
// XOR-swizzled smem). Source reads streamed (__ldcs): single use.
// ---------------------------------------------------------------------------
#define TSTRIDE 68
__global__ __launch_bounds__(256) void transpose_kernel(const float* __restrict__ src) {
    __shared__ float tileT[64 * TSTRIDE];

    const int batch = blockIdx.z;
    const int p0 = blockIdx.x * 64;
    const int c0 = blockIdx.y * 64;
    const float* s = src + (size_t)batch * C * HW;
    __half*      d = g_feat + (size_t)batch * HW * C;

    {
        const int tx = threadIdx.x & 15;
        const int ty = threadIdx.x >> 4;
        const float* rb = s + (size_t)(c0 + ty * 4) * HW + p0 + tx * 4;
        const float4 v0 = __ldcs((const float4*)(rb));
        const float4 v1 = __ldcs((const float4*)(rb + HW));
        const float4 v2 = __ldcs((const float4*)(rb + 2 * (size_t)HW));
        const float4 v3 = __ldcs((const float4*)(rb + 3 * (size_t)HW));

        float* wb = &tileT[(4 * tx) * TSTRIDE + 4 * ((ty ^ tx) & 15)];
        *(float4*)(wb + 0 * TSTRIDE) = make_float4(v0.x, v1.x, v2.x, v3.x);
        *(float4*)(wb + 1 * TSTRIDE) = make_float4(v0.y, v1.y, v2.y, v3.y);
        *(float4*)(wb + 2 * TSTRIDE) = make_float4(v0.z, v1.z, v2.z, v3.z);
        *(float4*)(wb + 3 * TSTRIDE) = make_float4(v0.w, v1.w, v2.w, v3.w);
    }
    __syncthreads();

    {
        const int c4 = threadIdx.x & 15;
        const int pr = threadIdx.x >> 4;
        #pragma unroll
        for (int k = 0; k < 4; k++) {
            const int p = pr + k * 16;
            const float4 w = *(const float4*)&tileT[p * TSTRIDE + 4 * ((c4 ^ (p >> 2)) & 15)];
            const __half2 h0 = __floats2half2_rn(w.x, w.y);
            const __half2 h1 = __floats2half2_rn(w.z, w.w);
            uint2 u;
            u.x = *reinterpret_cast<const unsigned int*>(&h0);
            u.y = *reinterpret_cast<const unsigned int*>(&h1);
            *reinterpret_cast<uint2*>(d + (size_t)(p0 + p) * C + c0 + c4 * 4) = u;
        }
    }
}

// ---------------------------------------------------------------------------
// Kernel 2: ROI-align gather. Block = (roi, oh-pair), 448 threads =
// 32 channel-groups (8ch, uint4) x 14 lanes; each lane exactly 2 samples
// (MLP=4 body, 32 regs, 4 blocks/SM).
// smem: quad q at sample s lives at word 128*(q&1) + 4*((q>>1) ^ ((s>>2)&7)),
// row stride 260.  Store = cg^E permutation (conflict-free STS.128).
// Writeback: one unit per thread (q = t/7, jq = t%7): 4x LDS.128 ->
// 4x4 register transpose -> 4x STG.128 (dense 16B stores, streamed).
// ---------------------------------------------------------------------------
#define CPAD 260

__global__ __launch_bounds__(448, 4) void roi_gather_kernel(
    const float* __restrict__ rois, float* __restrict__ out)
{
    const int blk  = blockIdx.x;
    const int r    = blk / 7;
    const int oh0  = (blk - r * 7) * 2;
    const int t    = threadIdx.x;
    const int cg   = t & 31;    // channel group: channels 8cg..8cg+7
    const int lane = t >> 5;    // 0..13 = ow

    const float bf = __ldg(&rois[r * 5 + 0]);
    const float x1 = __ldg(&rois[r * 5 + 1]);
    const float y1 = __ldg(&rois[r * 5 + 2]);
    const float x2 = __ldg(&rois[r * 5 + 3]);
    const float y2 = __ldg(&rois[r * 5 + 4]);
    const int  b   = (int)bf;

    const uint4* f4 = reinterpret_cast<const uint4*>(g_feat) + (size_t)b * HW * 32;

    __shared__ float sout[28 * CPAD];   // 29.1 KB

    // x-geometry shared by both samples (same ow)
    const float gx  = ((float)lane + 0.5f) * (1.0f / OW);
    const float fx  = (x1 + gx * (x2 - x1)) * SCALE - 0.5f;
    const float x0f = floorf(fx);
    const float lx  = fx - x0f;
    const int   xi0 = (int)x0f;
    const int   xi1 = xi0 + 1;
    const float wx0 = (1.0f - lx) * ((xi0 >= 0 && xi0 < W) ? 1.0f : 0.0f);
    const float wx1 = lx * ((xi1 >= 0 && xi1 < W) ? 1.0f : 0.0f);
    const int   x0c = min(max(xi0, 0), W - 1);
    const int   x1c = min(max(xi1, 0), W - 1);

    #pragma unroll
    for (int k = 0; k < 2; k++) {
        const int s  = lane + k * 14;
        const int oh = oh0 + k;

        const float gy  = ((float)oh + 0.5f) * (1.0f / OH);
        const float fy  = (y1 + gy * (y2 - y1)) * SCALE - 0.5f;
        const float y0f = floorf(fy);
        const float ly  = fy - y0f;
        const int   yi0 = (int)y0f;
        const int   yi1 = yi0 + 1;
        const float wy0 = (1.0f - ly) * ((yi0 >= 0 && yi0 < H) ? 1.0f : 0.0f);
        const float wy1 = ly * ((yi1 >= 0 && yi1 < H) ? 1.0f : 0.0f);
        const int   y0c = min(max(yi0, 0), H - 1);
        const int   y1c = min(max(yi1, 0), H - 1);

        const float w00 = wy0 * wx0;
        const float w01 = wy0 * wx1;
        const float w10 = wy1 * wx0;
        const float w11 = wy1 * wx1;

        // Unconditional, front-batched corner loads (MLP=4)
        const uint4 u00 = __ldg(&f4[(size_t)(y0c * W + x0c) * 32 + cg]);
        const uint4 u01 = __ldg(&f4[(size_t)(y0c * W + x1c) * 32 + cg]);
        const uint4 u10 = __ldg(&f4[(size_t)(y1c * W + x0c) * 32 + cg]);
        const uint4 u11 = __ldg(&f4[(size_t)(y1c * W + x1c) * 32 + cg]);

        float o0, o1, o2, o3, o4, o5, o6, o7;
        #define BLEND(CMP, OA, OB)                                                        \
            {                                                                             \
                const float2 a = __half22float2(*reinterpret_cast<const __half2*>(&u00.CMP)); \
                const float2 bq = __half22float2(*reinterpret_cast<const __half2*>(&u01.CMP)); \
                const float2 c = __half22float2(*reinterpret_cast<const __half2*>(&u10.CMP)); \
                const float2 dq = __half22float2(*reinterpret_cast<const __half2*>(&u11.CMP)); \
                OA = fmaf(w00, a.x, fmaf(w01, bq.x, fmaf(w10, c.x, w11 * dq.x)));         \
                OB = fmaf(w00, a.y, fmaf(w01, bq.y, fmaf(w10, c.y, w11 * dq.y)));         \
            }
        BLEND(x, o0, o1)
        BLEND(y, o2, o3)
        BLEND(z, o4, o5)
        BLEND(w, o6, o7)
        #undef BLEND

        const int E = (s >> 2) & 7;
        float* sb = &sout[s * CPAD + 4 * (cg ^ E)];
        *(float4*)(sb)       = make_float4(o0, o1, o2, o3);   // quad 2cg
        *(float4*)(sb + 128) = make_float4(o4, o5, o6, o7);   // quad 2cg+1
    }
    __syncthreads();

    // Writeback: 448 units = 64 quads x 7 sample-quads; exactly 1 per thread.
    {
        const int q  = t / 7;            // channel quad: channels 4q..4q+3
        const int jq = t - q * 7;        // sample quad:  samples 4jq..4jq+3
        const int jj0  = jq * 4;
        const int woff = ((q & 1) << 7) + 4 * ((q >> 1) ^ jq);

        const float4 v0 = *(const float4*)&sout[(jj0 + 0) * CPAD + woff];
        const float4 v1 = *(const float4*)&sout[(jj0 + 1) * CPAD + woff];
        const float4 v2 = *(const float4*)&sout[(jj0 + 2) * CPAD + woff];
        const float4 v3 = *(const float4*)&sout[(jj0 + 3) * CPAD + woff];

        float* ob = out + (size_t)r * C * (OH * OW)
                        + (size_t)(q * 4) * (OH * OW) + oh0 * OW + jj0;
        __stcs((float4*)(ob),                 make_float4(v0.x, v1.x, v2.x, v3.x));
        __stcs((float4*)(ob +     (OH * OW)), make_float4(v0.y, v1.y, v2.y, v3.y));
        __stcs((float4*)(ob + 2 * (OH * OW)), make_float4(v0.z, v1.z, v2.z, v3.z));
        __stcs((float4*)(ob + 3 * (OH * OW)), make_float4(v0.w, v1.w, v2.w, v3.w));
    }
}

// ---------------------------------------------------------------------------
extern "C" void kernel_launch(void* const* d_in, const int* in_sizes, int n_in,
                              void* d_out, int out_size) {
    const float* features = (const float*)d_in[0];
    const float* rois     = (const float*)d_in[1];
    if (n_in >= 2 && in_sizes[0] == R * 5) {
        features = (const float*)d_in[1];
        rois     = (const float*)d_in[0];
    }
    float* out = (float*)d_out;

    dim3 tgrid(HW / 64, C / 64, B);   // (1050, 4, 2)
    transpose_kernel<<<tgrid, 256>>>(features);

    roi_gather_kernel<<<R * 7, 448>>>(rois, out);
}

// round 11
// speedup vs baseline: 1.1852x; 1.0277x over previous
#include <cuda_runtime.h>
#include <cuda_fp16.h>

// Problem constants
#define B  2
#define C  256
#define H  200
#define W  336
#define R  1000
#define OH 14
#define OW 14
#define HW (H * W)           // 67200
#define SCALE 0.25f

// NHWC features in fp16: 2*67200*256*2B = 68.8 MB
__device__ static __half g_feat[(size_t)B * HW * C];

// ---------------------------------------------------------------------------
// Kernel 1: NCHW fp32 -> NHWC fp16 transpose (4x4 register micro-transpose,
// XOR-swizzled smem). Source reads streamed (__ldcs): single use.
// ---------------------------------------------------------------------------
#define TSTRIDE 68
__global__ __launch_bounds__(256) void transpose_kernel(const float* __restrict__ src) {
    __shared__ float tileT[64 * TSTRIDE];

    const int batch = blockIdx.z;
    const int p0 = blockIdx.x * 64;
    const int c0 = blockIdx.y * 64;
    const float* s = src + (size_t)batch * C * HW;
    __half*      d = g_feat + (size_t)batch * HW * C;

    {
        const int tx = threadIdx.x & 15;
        const int ty = threadIdx.x >> 4;
        const float* rb = s + (size_t)(c0 + ty * 4) * HW + p0 + tx * 4;
        const float4 v0 = __ldcs((const float4*)(rb));
        const float4 v1 = __ldcs((const float4*)(rb + HW));
        const float4 v2 = __ldcs((const float4*)(rb + 2 * (size_t)HW));
        const float4 v3 = __ldcs((const float4*)(rb + 3 * (size_t)HW));

        float* wb = &tileT[(4 * tx) * TSTRIDE + 4 * ((ty ^ tx) & 15)];
        *(float4*)(wb + 0 * TSTRIDE) = make_float4(v0.x, v1.x, v2.x, v3.x);
        *(float4*)(wb + 1 * TSTRIDE) = make_float4(v0.y, v1.y, v2.y, v3.y);
        *(float4*)(wb + 2 * TSTRIDE) = make_float4(v0.z, v1.z, v2.z, v3.z);
        *(float4*)(wb + 3 * TSTRIDE) = make_float4(v0.w, v1.w, v2.w, v3.w);
    }
    __syncthreads();

    {
        const int c4 = threadIdx.x & 15;
        const int pr = threadIdx.x >> 4;
        #pragma unroll
        for (int k = 0; k < 4; k++) {
            const int p = pr + k * 16;
            const float4 w = *(const float4*)&tileT[p * TSTRIDE + 4 * ((c4 ^ (p >> 2)) & 15)];
            const __half2 h0 = __floats2half2_rn(w.x, w.y);
            const __half2 h1 = __floats2half2_rn(w.z, w.w);
            uint2 u;
            u.x = *reinterpret_cast<const unsigned int*>(&h0);
            u.y = *reinterpret_cast<const unsigned int*>(&h1);
            *reinterpret_cast<uint2*>(d + (size_t)(p0 + p) * C + c0 + c4 * 4) = u;
        }
    }
}

// ---------------------------------------------------------------------------
// Kernel 2: ROI-align gather. Block = (roi, oh-pair), 448 threads =
// 32 channel-groups (8ch, uint4) x 14 lanes; each lane exactly 2 samples
// (MLP=4, 4 blocks/SM).
// Staging in fp16: sample s row of 128 words (256 half).  Thread cg stores
// one uint4 (8 ch as 4 half2) at word 4*(cg^E), E = s>>2  -> STS.128
// lane-permuted, conflict-free.  Row stride 132 words.
// Writeback: unit per thread (q = t/7 channel-quad, jq = t%7 sample-quad):
// 4x LDS.64 at word W = 4*((q>>1)^jq) + 2*(q&1) -> cvt -> 4x STG.128 dense.
// ---------------------------------------------------------------------------
#define RW 132   // smem row stride in 32-bit words

__global__ __launch_bounds__(448, 4) void roi_gather_kernel(
    const float* __restrict__ rois, float* __restrict__ out)
{
    const int blk  = blockIdx.x;
    const int r    = blk / 7;
    const int oh0  = (blk - r * 7) * 2;
    const int t    = threadIdx.x;
    const int cg   = t & 31;    // channel group: channels 8cg..8cg+7
    const int lane = t >> 5;    // 0..13 = ow

    const float bf = __ldg(&rois[r * 5 + 0]);
    const float x1 = __ldg(&rois[r * 5 + 1]);
    const float y1 = __ldg(&rois[r * 5 + 2]);
    const float x2 = __ldg(&rois[r * 5 + 3]);
    const float y2 = __ldg(&rois[r * 5 + 4]);
    const int  b   = (int)bf;

    const uint4* f4 = reinterpret_cast<const uint4*>(g_feat) + (size_t)b * HW * 32;

    __shared__ unsigned int sout[28 * RW];   // 14.8 KB (fp16 staging)

    // x-geometry shared by both samples (same ow)
    const float gx  = ((float)lane + 0.5f) * (1.0f / OW);
    const float fx  = (x1 + gx * (x2 - x1)) * SCALE - 0.5f;
    const float x0f = floorf(fx);
    const float lx  = fx - x0f;
    const int   xi0 = (int)x0f;
    const int   xi1 = xi0 + 1;
    const float wx0 = (1.0f - lx) * ((xi0 >= 0 && xi0 < W) ? 1.0f : 0.0f);
    const float wx1 = lx * ((xi1 >= 0 && xi1 < W) ? 1.0f : 0.0f);
    const int   x0c = min(max(xi0, 0), W - 1);
    const int   x1c = min(max(xi1, 0), W - 1);

    #pragma unroll
    for (int k = 0; k < 2; k++) {
        const int s  = lane + k * 14;
        const int oh = oh0 + k;

        const float gy  = ((float)oh + 0.5f) * (1.0f / OH);
        const float fy  = (y1 + gy * (y2 - y1)) * SCALE - 0.5f;
        const float y0f = floorf(fy);
        const float ly  = fy - y0f;
        const int   yi0 = (int)y0f;
        const int   yi1 = yi0 + 1;
        const float wy0 = (1.0f - ly) * ((yi0 >= 0 && yi0 < H) ? 1.0f : 0.0f);
        const float wy1 = ly * ((yi1 >= 0 && yi1 < H) ? 1.0f : 0.0f);
        const int   y0c = min(max(yi0, 0), H - 1);
        const int   y1c = min(max(yi1, 0), H - 1);

        const float w00 = wy0 * wx0;
        const float w01 = wy0 * wx1;
        const float w10 = wy1 * wx0;
        const float w11 = wy1 * wx1;

        // Unconditional, front-batched corner loads (MLP=4)
        const uint4 u00 = __ldg(&f4[(size_t)(y0c * W + x0c) * 32 + cg]);
        const uint4 u01 = __ldg(&f4[(size_t)(y0c * W + x1c) * 32 + cg]);
        const uint4 u10 = __ldg(&f4[(size_t)(y1c * W + x0c) * 32 + cg]);
        const uint4 u11 = __ldg(&f4[(size_t)(y1c * W + x1c) * 32 + cg]);

        float o0, o1, o2, o3, o4, o5, o6, o7;
        #define BLEND(CMP, OA, OB)                                                        \
            {                                                                             \
                const float2 a = __half22float2(*reinterpret_cast<const __half2*>(&u00.CMP)); \
                const float2 bq = __half22float2(*reinterpret_cast<const __half2*>(&u01.CMP)); \
                const float2 c = __half22float2(*reinterpret_cast<const __half2*>(&u10.CMP)); \
                const float2 dq = __half22float2(*reinterpret_cast<const __half2*>(&u11.CMP)); \
                OA = fmaf(w00, a.x, fmaf(w01, bq.x, fmaf(w10, c.x, w11 * dq.x)));         \
                OB = fmaf(w00, a.y, fmaf(w01, bq.y, fmaf(w10, c.y, w11 * dq.y)));         \
            }
        BLEND(x, o0, o1)
        BLEND(y, o2, o3)
        BLEND(z, o4, o5)
        BLEND(w, o6, o7)
        #undef BLEND

        // Pack to fp16 and stage: one STS.128 per sample.
        const __half2 h01 = __floats2half2_rn(o0, o1);
        const __half2 h23 = __floats2half2_rn(o2, o3);
        const __half2 h45 = __floats2half2_rn(o4, o5);
        const __half2 h67 = __floats2half2_rn(o6, o7);
        const int E = s >> 2;
        uint4 pk;
        pk.x = *reinterpret_cast<const unsigned int*>(&h01);
        pk.y = *reinterpret_cast<const unsigned int*>(&h23);
        pk.z = *reinterpret_cast<const unsigned int*>(&h45);
        pk.w = *reinterpret_cast<const unsigned int*>(&h67);
        *reinterpret_cast<uint4*>(&sout[s * RW + 4 * (cg ^ E)]) = pk;
    }
    __syncthreads();

    // Writeback: 448 units = 64 channel-quads x 7 sample-quads; 1 per thread.
    {
        const int q  = t / 7;            // channel quad: channels 4q..4q+3
        const int jq = t - q * 7;        // sample quad:  samples 4jq..4jq+3
        const int jj0 = jq * 4;
        const int Wd  = 4 * ((q >> 1) ^ jq) + 2 * (q & 1);

        float2 fa[4], fb[4];
        #pragma unroll
        for (int i = 0; i < 4; i++) {
            const uint2 v = *reinterpret_cast<const uint2*>(&sout[(jj0 + i) * RW + Wd]);
            fa[i] = __half22float2(*reinterpret_cast<const __half2*>(&v.x)); // ch 4q,4q+1
            fb[i] = __half22float2(*reinterpret_cast<const __half2*>(&v.y)); // ch 4q+2,4q+3
        }

        float* ob = out + (size_t)r * C * (OH * OW)
                        + (size_t)(q * 4) * (OH * OW) + oh0 * OW + jj0;
        __stcs((float4*)(ob),                 make_float4(fa[0].x, fa[1].x, fa[2].x, fa[3].x));
        __stcs((float4*)(ob +     (OH * OW)), make_float4(fa[0].y, fa[1].y, fa[2].y, fa[3].y));
        __stcs((float4*)(ob + 2 * (OH * OW)), make_float4(fb[0].x, fb[1].x, fb[2].x, fb[3].x));
        __stcs((float4*)(ob + 3 * (OH * OW)), make_float4(fb[0].y, fb[1].y, fb[2].y, fb[3].y));
    }
}

// ---------------------------------------------------------------------------
extern "C" void kernel_launch(void* const* d_in, const int* in_sizes, int n_in,
                              void* d_out, int out_size) {
    const float* features = (const float*)d_in[0];
    const float* rois     = (const float*)d_in[1];
    if (n_in >= 2 && in_sizes[0] == R * 5) {
        features = (const float*)d_in[1];
        rois     = (const float*)d_in[0];
    }
    float* out = (float*)d_out;

    dim3 tgrid(HW / 64, C / 64, B);   // (1050, 4, 2)
    transpose_kernel<<<tgrid, 256>>>(features);

    roi_gather_kernel<<<R * 7, 448>>>(rois, out);
}